// round 14
// baseline (speedup 1.0000x reference)
#include <cuda_runtime.h>
#include <cuda_fp16.h>
#include <math.h>
#include <stdint.h>

// ---------------- problem constants ----------------
#define B_  8
#define S_  2048
#define HID 1024
#define L_  4
#define M_  (B_ * S_)    // 16384
#define N_  (2 * HID)    // 2048
#define K_  1024
#define CH_ 8192         // B*H channels
#define NCK 64           // scan chunks
#define CKS 32           // steps per chunk

// ---------------- GEMM tiling ----------------
#define BM 128
#define BN 256
#define NCHUNK 16        // K_/64
#define STAGES 2
#define GTHREADS 512

#define STAGE_BYTES 49152
#define OFF_A 0
#define OFF_B 16384
#define SMEM_BYTES (1024 + STAGES * STAGE_BYTES)   // 99328 -> 2 CTAs/SM

#define A_TILE_B 16384   // 128x64 fp16
#define W_TILE_B 32768   // 256x64 fp16

// ---------------- scratch (allocation-free rule) ----------------
__device__ uint32_t g_ab[(size_t)M_ * HID];   // packed half2 (a, b)
__device__ float    g_inp[(size_t)M_ * HID];
__device__ float    g_sumA[CH_ * NCK];
__device__ float    g_sumB[CH_ * NCK];
__device__ float    g_start[CH_ * NCK];
__device__ uint4    g_Ah[(size_t)M_ * K_ / 8];
__device__ uint4    g_Wh[(size_t)L_ * N_ * K_ / 8];

// ---------------- helpers ----------------
__device__ __forceinline__ uint32_t smem_u32(const void* p) {
    uint32_t a;
    asm("{ .reg .u64 t; cvta.to.shared.u64 t, %1; cvt.u32.u64 %0, t; }"
        : "=r"(a) : "l"(p));
    return a;
}
__device__ __forceinline__ void bulk_g2s(uint32_t dst, const void* src,
                                         uint32_t bytes, uint32_t mbar) {
    asm volatile(
        "cp.async.bulk.shared::cta.global.mbarrier::complete_tx::bytes "
        "[%0], [%1], %2, [%3];"
        :: "r"(dst), "l"(src), "r"(bytes), "r"(mbar) : "memory");
}
#define MBAR_INIT(a, c) \
    asm volatile("mbarrier.init.shared.b64 [%0], %1;" :: "r"(a), "r"((uint32_t)(c)) : "memory")
#define MBAR_EXPECT(a, b) \
    asm volatile("mbarrier.arrive.expect_tx.shared.b64 _, [%0], %1;" \
                 :: "r"(a), "r"((uint32_t)(b)) : "memory")
#define MBAR_WAIT(a, ph) do {                                                    \
    asm volatile(                                                                 \
        "{ .reg .pred P;\n"                                                       \
        "LAB_%=: mbarrier.try_wait.parity.acquire.cta.shared::cta.b64 P, [%0], %1, 0x989680;\n" \
        "@P bra.uni DONE_%=;\n"                                                   \
        "bra.uni LAB_%=;\n"                                                       \
        "DONE_%=: }"                                                              \
        :: "r"(a), "r"((uint32_t)(ph)) : "memory");                               \
} while (0)

__device__ __forceinline__ void ldm_x4(uint32_t* r, uint32_t addr) {
    asm volatile("ldmatrix.sync.aligned.m8n8.x4.shared.b16 {%0,%1,%2,%3}, [%4];"
                 : "=r"(r[0]), "=r"(r[1]), "=r"(r[2]), "=r"(r[3]) : "r"(addr));
}
__device__ __forceinline__ void mma_16816(float* c, const uint32_t* a,
                                          const uint32_t* b) {
    asm volatile(
        "mma.sync.aligned.m16n8k16.row.col.f32.f16.f16.f32 "
        "{%0,%1,%2,%3}, {%4,%5,%6,%7}, {%8,%9}, {%0,%1,%2,%3};"
        : "+f"(c[0]), "+f"(c[1]), "+f"(c[2]), "+f"(c[3])
        : "r"(a[0]), "r"(a[1]), "r"(a[2]), "r"(a[3]), "r"(b[0]), "r"(b[1]));
}

// gate/hidden pair -> packed half2 (a, b)
__device__ __forceinline__ uint32_t gate2ab(float gate, float hd) {
    float e1 = __expf(fminf(gate, 60.f));
    float e2 = __expf(fminf(hd, 0.f));
    float d1 = 1.f + e1, d2 = 1.f + e2;
    float rr = __fdividef(1.f, d1 * d2);
    float a  = rr * d2;            // sigma(-gate)
    float s2 = e2 * rr * d1;       // sigma(hd)  [hd<0 path]
    float z  = 1.f - a;            // sigma(gate)
    float gg = (hd >= 0.f) ? (hd + 0.5f) : s2;
    float bv = z * gg;
    __half2 h2 = __floats2half2_rn(a, bv);
    return *(uint32_t*)&h2;
}

// ---------------------------------------------------------------------------
// fp16 GEMM with fused gate transform: ab[m][p] = f(A@W^T + bias)
// 2 CTAs/SM double-buffered; W rows pre-interleaved (gate_p, hidden_p).
// ---------------------------------------------------------------------------
__global__ void __launch_bounds__(GTHREADS, 2)
gemm_mma(const char* __restrict__ Ah, const char* __restrict__ Wh,
         const float* __restrict__ bias, uint32_t* __restrict__ ab) {
    extern __shared__ __align__(1024) char smem[];
    const uint32_t sb = smem_u32(smem);
    const int tid = threadIdx.x;
    const int wid = tid >> 5, lid = tid & 31;
    const int wr = wid & 1;
    const int wc = wid >> 1;
    const int rowBase = blockIdx.y * BM;
    const int colBase = blockIdx.x * BN;

    if (tid == 0) {
#pragma unroll
        for (int s = 0; s < STAGES; ++s) MBAR_INIT(sb + s * 8, 1);
    }
    __syncthreads();

    auto issue = [&](int kc, int s) {
        uint32_t bar = sb + s * 8;
        uint32_t st = sb + 1024 + s * STAGE_BYTES;
        MBAR_EXPECT(bar, STAGE_BYTES);
        bulk_g2s(st + OFF_A, Ah + ((size_t)blockIdx.y * NCHUNK + kc) * A_TILE_B,
                 A_TILE_B, bar);
        bulk_g2s(st + OFF_B, Wh + ((size_t)blockIdx.x * NCHUNK + kc) * W_TILE_B,
                 W_TILE_B, bar);
    };

    if (tid == 0) { issue(0, 0); issue(1, 1); }

    float acc[4][4][4];
#pragma unroll
    for (int i = 0; i < 4; ++i)
#pragma unroll
        for (int j = 0; j < 4; ++j)
#pragma unroll
            for (int k = 0; k < 4; ++k) acc[i][j][k] = 0.f;

    const int a_r  = (lid & 7) + ((lid >> 3) & 1) * 8;
    const int a_kb = lid >> 4;
    const int b_r  = (lid & 7) + ((lid >> 4) & 1) * 8;
    const int b_kb = (lid >> 3) & 1;

    int ph[STAGES] = {0, 0};

    for (int kt = 0; kt < NCHUNK; ++kt) {
        const int s = kt & 1;
        MBAR_WAIT(sb + s * 8, ph[s]);
        ph[s] ^= 1;

        const uint32_t st = sb + 1024 + s * STAGE_BYTES;
#pragma unroll
        for (int ks = 0; ks < 4; ++ks) {
            uint32_t af[4][4], bf[2][4];
#pragma unroll
            for (int mt = 0; mt < 4; ++mt) {
                int r = wr * 64 + mt * 16 + a_r;
                int u = ks * 2 + a_kb;
                ldm_x4(af[mt], st + OFF_A + r * 128 + ((u ^ (r & 7)) << 4));
            }
#pragma unroll
            for (int np = 0; np < 2; ++np) {
                int n = wc * 32 + np * 16 + b_r;
                int u = ks * 2 + b_kb;
                ldm_x4(bf[np], st + OFF_B + n * 128 + ((u ^ (n & 7)) << 4));
            }
#pragma unroll
            for (int mt = 0; mt < 4; ++mt)
#pragma unroll
                for (int nt = 0; nt < 4; ++nt) {
                    uint32_t bb[2] = { bf[nt >> 1][(nt & 1) * 2],
                                       bf[nt >> 1][(nt & 1) * 2 + 1] };
                    mma_16816(acc[mt][nt], af[mt], bb);
                }
        }
        __syncthreads();
        if (tid == 0 && kt + 2 < NCHUNK) issue(kt + 2, s);
    }

    // fused epilogue: bias + gate transform + packed half2(a,b) store
    const int g = lid >> 2, tig = lid & 3;
#pragma unroll
    for (int mt = 0; mt < 4; ++mt) {
        int row0 = rowBase + wr * 64 + mt * 16 + g;
#pragma unroll
        for (int nt = 0; nt < 4; ++nt) {
            int p = ((colBase + wc * 32 + nt * 8) >> 1) + tig;
            float bg = bias[p], bh = bias[HID + p];
            float* c = acc[mt][nt];
            ab[(size_t)row0 * HID + p]       = gate2ab(c[0] + bg, c[1] + bh);
            ab[(size_t)(row0 + 8) * HID + p] = gate2ab(c[2] + bg, c[3] + bh);
        }
    }
}

// ---------------------------------------------------------------------------
// fp32 -> fp16 tiled+swizzled. PAIR=true interleaves W rows (gate_p, hid_p).
// ---------------------------------------------------------------------------
template <int TR, bool PAIR>
__global__ void conv_tiled(const float* __restrict__ in,
                           uint4* __restrict__ hi, int nunits) {
    int i = blockIdx.x * blockDim.x + threadIdx.x;
    if (i >= nunits) return;
    int m  = i >> 7;
    int ku = i & 127;
    int kc = ku >> 3, u = ku & 7;
    int dm = PAIR ? (2 * (m & (HID - 1)) + (m >> 10)) : m;
    int mb = dm / TR, r = dm % TR;

    const float4* p = (const float4*)(in + (size_t)m * K_ + ku * 8);
    float4 v0 = p[0], v1 = p[1];
    float vv[8] = {v0.x, v0.y, v0.z, v0.w, v1.x, v1.y, v1.z, v1.w};

    uint32_t hw[4];
#pragma unroll
    for (int j = 0; j < 4; ++j) {
        __half h0 = __float2half_rn(vv[2 * j]);
        __half h1 = __float2half_rn(vv[2 * j + 1]);
        hw[j] = (uint32_t)__half_as_ushort(h0) |
                ((uint32_t)__half_as_ushort(h1) << 16);
    }
    size_t tile = ((size_t)mb * NCHUNK + kc) * (TR * 8);
    hi[tile + r * 8 + (u ^ (r & 7))] = make_uint4(hw[0], hw[1], hw[2], hw[3]);
}

// ---------------------------------------------------------------------------
// Phase 1: per-chunk (A,B) summaries, 8 channels/thread. grid (8, NCK) x 128
// ---------------------------------------------------------------------------
__global__ void __launch_bounds__(128) scan_sum() {
    const int cg = blockIdx.x * 128 + threadIdx.x;   // 0..1023
    const int ck = blockIdx.y;
    const int b = cg >> 7;
    const int hid0 = (cg & 127) * 8;
    const size_t rowbase = (size_t)b * S_ + ck * CKS;

    float A[8], Bc[8];
#pragma unroll
    for (int j = 0; j < 8; ++j) { A[j] = 1.f; Bc[j] = 0.f; }

#pragma unroll 4
    for (int s = 0; s < CKS; ++s) {
        const uint4* abp = (const uint4*)(g_ab + (rowbase + s) * HID + hid0);
        uint4 u0 = abp[0], u1 = abp[1];
        uint32_t uw[8] = {u0.x, u0.y, u0.z, u0.w, u1.x, u1.y, u1.z, u1.w};
#pragma unroll
        for (int j = 0; j < 8; ++j) {
            __half2 h2 = *(__half2*)&uw[j];
            float a = __low2float(h2), bv = __high2float(h2);
            Bc[j] = fmaf(a, Bc[j], bv);
            A[j] *= a;
        }
    }
    const int ch0 = b * HID + hid0;
#pragma unroll
    for (int j = 0; j < 8; ++j) {
        g_sumA[(ch0 + j) * NCK + ck] = A[j];
        g_sumB[(ch0 + j) * NCK + ck] = Bc[j];
    }
}

// ---------------------------------------------------------------------------
// Phase 2: 64-chunk scan per channel; one warp per channel, 2 chunks/lane.
// ---------------------------------------------------------------------------
__global__ void __launch_bounds__(256) scan_phase2(const float* __restrict__ h0) {
    const int gt = blockIdx.x * 256 + threadIdx.x;
    const int ch = gt >> 5;
    const int lane = gt & 31;

    float2 a2 = ((const float2*)(g_sumA + ch * NCK))[lane];
    float2 b2 = ((const float2*)(g_sumB + ch * NCK))[lane];
    float A0 = a2.x, B0 = b2.x;      // chunk 2*lane
    float A1 = a2.y, B1 = b2.y;      // chunk 2*lane+1

    // pair compose: f_{2l+1} o f_{2l}
    float A = A1 * A0;
    float Bv = fmaf(A1, B0, B1);
#pragma unroll
    for (int off = 1; off < 32; off <<= 1) {
        float pA = __shfl_up_sync(0xFFFFFFFF, A, off);
        float pB = __shfl_up_sync(0xFFFFFFFF, Bv, off);
        if (lane >= off) {
            Bv = fmaf(A, pB, Bv);
            A  = pA * A;
        }
    }
    float eA = __shfl_up_sync(0xFFFFFFFF, A, 1);
    float eB = __shfl_up_sync(0xFFFFFFFF, Bv, 1);
    if (lane == 0) { eA = 1.f; eB = 0.f; }

    float x = h0[ch];
    float h0g = (x >= 0.f) ? (x + 0.5f)
                           : __fdividef(__expf(x), 1.f + __expf(x));
    float s0 = fmaf(eA, h0g, eB);     // start of chunk 2*lane
    float s1 = fmaf(A0, s0, B0);      // start of chunk 2*lane+1
    g_start[(2 * lane) * CH_ + ch]     = s0;
    g_start[(2 * lane + 1) * CH_ + ch] = s1;
}

// ---------------------------------------------------------------------------
// Phase 3: 8 channels/thread local scan + residual; optionally emits next
// layer's tiled fp16 A. grid (8, NCK) x 128.
// ---------------------------------------------------------------------------
template <bool EMIT_A>
__global__ void __launch_bounds__(128)
scan_phase3(const float* __restrict__ resid, float* __restrict__ outp,
            float* __restrict__ finals) {
    const int cg = blockIdx.x * 128 + threadIdx.x;   // 0..1023
    const int ck = blockIdx.y;
    const int b = cg >> 7;
    const int ku = cg & 127;
    const int hid0 = ku * 8;
    const int ch0 = b * HID + hid0;
    const size_t rowbase = (size_t)b * S_ + ck * CKS;
    const int kc = ku >> 3, uu = ku & 7;

    float h[8];
    {
        const float4* sp = (const float4*)(g_start + ck * CH_ + ch0);
        float4 s0 = sp[0], s1 = sp[1];
        h[0] = s0.x; h[1] = s0.y; h[2] = s0.z; h[3] = s0.w;
        h[4] = s1.x; h[5] = s1.y; h[6] = s1.z; h[7] = s1.w;
    }

#pragma unroll 4
    for (int s = 0; s < CKS; ++s) {
        size_t row = rowbase + s;
        const uint4* abp = (const uint4*)(g_ab + row * HID + hid0);
        uint4 u0 = abp[0], u1 = abp[1];
        const float4* rp = (const float4*)(resid + row * HID + hid0);
        float4 r0 = rp[0], r1 = rp[1];

        uint32_t uw[8] = {u0.x, u0.y, u0.z, u0.w, u1.x, u1.y, u1.z, u1.w};
        float rr[8] = {r0.x, r0.y, r0.z, r0.w, r1.x, r1.y, r1.z, r1.w};
        float ov[8];
#pragma unroll
        for (int j = 0; j < 8; ++j) {
            __half2 h2 = *(__half2*)&uw[j];
            h[j] = fmaf(__low2float(h2), h[j], __high2float(h2));
            ov[j] = h[j] + rr[j];
        }
        float4* op = (float4*)(outp + row * HID + hid0);
        op[0] = make_float4(ov[0], ov[1], ov[2], ov[3]);
        op[1] = make_float4(ov[4], ov[5], ov[6], ov[7]);

        if (EMIT_A) {
            uint32_t hw[4];
#pragma unroll
            for (int j = 0; j < 4; ++j) {
                __half a0 = __float2half_rn(ov[2 * j]);
                __half a1 = __float2half_rn(ov[2 * j + 1]);
                hw[j] = (uint32_t)__half_as_ushort(a0) |
                        ((uint32_t)__half_as_ushort(a1) << 16);
            }
            int mb = (int)(row >> 7), r = (int)(row & 127);
            g_Ah[((size_t)mb * NCHUNK + kc) * 1024 + r * 8 + (uu ^ (r & 7))] =
                make_uint4(hw[0], hw[1], hw[2], hw[3]);
        }
    }

    if (ck == NCK - 1) {
        float4* fp = (float4*)(finals + ch0);
        fp[0] = make_float4(h[0], h[1], h[2], h[3]);
        fp[1] = make_float4(h[4], h[5], h[6], h[7]);
    }
}

// ---------------------------------------------------------------------------
// Launcher
// ---------------------------------------------------------------------------
extern "C" void kernel_launch(void* const* d_in, const int* in_sizes, int n_in,
                              void* d_out, int out_size) {
    const float* x  = (const float*)d_in[0];
    const float* h  = (const float*)d_in[1];
    const float* W0 = (const float*)d_in[2];
    const float* b0 = (const float*)d_in[3];
    const float* Wl = (const float*)d_in[4];
    const float* bl = (const float*)d_in[5];

    float* out    = (float*)d_out;
    float* finals = out + (size_t)M_ * HID;

    float* inp;
    uint32_t* ab;
    uint4 *Ah, *Wh;
    cudaGetSymbolAddress((void**)&inp, g_inp);
    cudaGetSymbolAddress((void**)&ab,  g_ab);
    cudaGetSymbolAddress((void**)&Ah,  g_Ah);
    cudaGetSymbolAddress((void**)&Wh,  g_Wh);

    cudaFuncSetAttribute(gemm_mma, cudaFuncAttributeMaxDynamicSharedMemorySize,
                         SMEM_BYTES);

    const int nAu = M_ * K_ / 8;
    const int nWu = N_ * K_ / 8;   // per-layer W units
    dim3 ggrid(N_ / BN, M_ / BM);     // (8, 128)
    dim3 sgrid(8, NCK);               // (8, 64)

    // all W conversions + layer-0 A conversion upfront
    conv_tiled<BM, false><<<(nAu + 255) / 256, 256>>>(x, Ah, nAu);
    conv_tiled<BN, true><<<(nWu + 255) / 256, 256>>>(W0, Wh, nWu);
    for (int l = 1; l < L_; ++l)
        conv_tiled<BN, true><<<(nWu + 255) / 256, 256>>>(
            Wl + (size_t)(l - 1) * N_ * K_, Wh + (size_t)l * nWu, nWu);

    for (int l = 0; l < L_; ++l) {
        const float* b = (l == 0) ? b0 : (bl + (size_t)(l - 1) * N_);
        const float* src = (l == 0) ? x : inp;

        gemm_mma<<<ggrid, GTHREADS, SMEM_BYTES>>>(
            (const char*)Ah, (const char*)(Wh + (size_t)l * nWu), b, ab);

        scan_sum<<<sgrid, 128>>>();
        scan_phase2<<<CH_ * 32 / 256, 256>>>(h + (size_t)l * CH_);
        float* ob = (l == L_ - 1) ? out : inp;
        if (l == L_ - 1)
            scan_phase3<false><<<sgrid, 128>>>(src, ob,
                                               finals + (size_t)l * CH_);
        else
            scan_phase3<true><<<sgrid, 128>>>(src, ob,
                                              finals + (size_t)l * CH_);
    }
}

// round 15
// speedup vs baseline: 2.5645x; 2.5645x over previous
#include <cuda_runtime.h>
#include <cuda_fp16.h>
#include <math.h>
#include <stdint.h>

// ---------------- problem constants ----------------
#define B_  8
#define S_  2048
#define HID 1024
#define L_  4
#define M_  (B_ * S_)    // 16384
#define N_  (2 * HID)    // 2048
#define K_  1024
#define CH_ 8192         // B*H channels
#define NCK 64           // scan chunks
#define CKS 32           // steps per chunk

// ---------------- GEMM tiling ----------------
#define BM 128
#define BN 256
#define NCHUNK 16        // K_/64
#define STAGES 4
#define GTHREADS 512

#define STAGE_BYTES 49152
#define OFF_A 0
#define OFF_B 16384
#define SMEM_BYTES (1024 + STAGES * STAGE_BYTES)   // 197632, 1 CTA/SM

#define A_TILE_B 16384   // 128x64 fp16
#define W_TILE_B 32768   // 256x64 fp16

// ---------------- scratch (allocation-free rule) ----------------
__device__ uint32_t g_ab[(size_t)M_ * HID];   // packed half2 (a, b)
__device__ float    g_inp[(size_t)M_ * HID];
__device__ float    g_sumA[CH_ * NCK];
__device__ float    g_sumB[CH_ * NCK];
__device__ float    g_start[CH_ * NCK];
__device__ uint4    g_Ah[(size_t)M_ * K_ / 8];
__device__ uint4    g_Wh[(size_t)L_ * N_ * K_ / 8];

// ---------------- helpers ----------------
__device__ __forceinline__ uint32_t smem_u32(const void* p) {
    uint32_t a;
    asm("{ .reg .u64 t; cvta.to.shared.u64 t, %1; cvt.u32.u64 %0, t; }"
        : "=r"(a) : "l"(p));
    return a;
}
__device__ __forceinline__ void bulk_g2s(uint32_t dst, const void* src,
                                         uint32_t bytes, uint32_t mbar) {
    asm volatile(
        "cp.async.bulk.shared::cta.global.mbarrier::complete_tx::bytes "
        "[%0], [%1], %2, [%3];"
        :: "r"(dst), "l"(src), "r"(bytes), "r"(mbar) : "memory");
}
#define MBAR_INIT(a, c) \
    asm volatile("mbarrier.init.shared.b64 [%0], %1;" :: "r"(a), "r"((uint32_t)(c)) : "memory")
#define MBAR_EXPECT(a, b) \
    asm volatile("mbarrier.arrive.expect_tx.shared.b64 _, [%0], %1;" \
                 :: "r"(a), "r"((uint32_t)(b)) : "memory")
#define MBAR_WAIT(a, ph) do {                                                    \
    asm volatile(                                                                 \
        "{ .reg .pred P;\n"                                                       \
        "LAB_%=: mbarrier.try_wait.parity.acquire.cta.shared::cta.b64 P, [%0], %1, 0x989680;\n" \
        "@P bra.uni DONE_%=;\n"                                                   \
        "bra.uni LAB_%=;\n"                                                       \
        "DONE_%=: }"                                                              \
        :: "r"(a), "r"((uint32_t)(ph)) : "memory");                               \
} while (0)

__device__ __forceinline__ void ldm_x4(uint32_t* r, uint32_t addr) {
    asm volatile("ldmatrix.sync.aligned.m8n8.x4.shared.b16 {%0,%1,%2,%3}, [%4];"
                 : "=r"(r[0]), "=r"(r[1]), "=r"(r[2]), "=r"(r[3]) : "r"(addr));
}
__device__ __forceinline__ void mma_16816(float* c, const uint32_t* a,
                                          const uint32_t* b) {
    asm volatile(
        "mma.sync.aligned.m16n8k16.row.col.f32.f16.f16.f32 "
        "{%0,%1,%2,%3}, {%4,%5,%6,%7}, {%8,%9}, {%0,%1,%2,%3};"
        : "+f"(c[0]), "+f"(c[1]), "+f"(c[2]), "+f"(c[3])
        : "r"(a[0]), "r"(a[1]), "r"(a[2]), "r"(a[3]), "r"(b[0]), "r"(b[1]));
}

// gate/hidden pair -> packed half2 (a, b)
__device__ __forceinline__ uint32_t gate2ab(float gate, float hd) {
    float e1 = __expf(fminf(gate, 60.f));
    float e2 = __expf(fminf(hd, 0.f));
    float d1 = 1.f + e1, d2 = 1.f + e2;
    float rr = __fdividef(1.f, d1 * d2);
    float a  = rr * d2;            // sigma(-gate)
    float s2 = e2 * rr * d1;       // sigma(hd)  [hd<0 path]
    float z  = 1.f - a;            // sigma(gate)
    float gg = (hd >= 0.f) ? (hd + 0.5f) : s2;
    float bv = z * gg;
    __half2 h2 = __floats2half2_rn(a, bv);
    return *(uint32_t*)&h2;
}

// ---------------------------------------------------------------------------
// fp16 GEMM with fused gate transform: ab[m][p] = f(A@W^T + bias)
// R11-proven config: 4-stage pipeline, 1 CTA/SM, issue-ahead prefetch.
// W rows pre-interleaved (gate_p, hidden_p).
// ---------------------------------------------------------------------------
__global__ void __launch_bounds__(GTHREADS, 1)
gemm_mma(const char* __restrict__ Ah, const char* __restrict__ Wh,
         const float* __restrict__ bias, uint32_t* __restrict__ ab) {
    extern __shared__ __align__(1024) char smem[];
    const uint32_t sb = smem_u32(smem);
    const int tid = threadIdx.x;
    const int wid = tid >> 5, lid = tid & 31;
    const int wr = wid & 1;
    const int wc = wid >> 1;
    const int rowBase = blockIdx.y * BM;
    const int colBase = blockIdx.x * BN;

    if (tid == 0) {
#pragma unroll
        for (int s = 0; s < STAGES; ++s) MBAR_INIT(sb + s * 8, 1);
    }
    __syncthreads();

    auto issue = [&](int kc, int s) {
        uint32_t bar = sb + s * 8;
        uint32_t st = sb + 1024 + s * STAGE_BYTES;
        MBAR_EXPECT(bar, STAGE_BYTES);
        bulk_g2s(st + OFF_A, Ah + ((size_t)blockIdx.y * NCHUNK + kc) * A_TILE_B,
                 A_TILE_B, bar);
        bulk_g2s(st + OFF_B, Wh + ((size_t)blockIdx.x * NCHUNK + kc) * W_TILE_B,
                 W_TILE_B, bar);
    };

    if (tid == 0) { issue(0, 0); issue(1, 1); issue(2, 2); }

    float acc[4][4][4];
#pragma unroll
    for (int i = 0; i < 4; ++i)
#pragma unroll
        for (int j = 0; j < 4; ++j)
#pragma unroll
            for (int k = 0; k < 4; ++k) acc[i][j][k] = 0.f;

    const int a_r  = (lid & 7) + ((lid >> 3) & 1) * 8;
    const int a_kb = lid >> 4;
    const int b_r  = (lid & 7) + ((lid >> 4) & 1) * 8;
    const int b_kb = (lid >> 3) & 1;

    int ph[STAGES] = {0, 0, 0, 0};

    for (int kt = 0; kt < NCHUNK; ++kt) {
        const int s = kt % STAGES;
        MBAR_WAIT(sb + s * 8, ph[s]);
        ph[s] ^= 1;
        if (tid == 0 && kt + 3 < NCHUNK) issue(kt + 3, (kt + 3) % STAGES);

        const uint32_t st = sb + 1024 + s * STAGE_BYTES;
#pragma unroll
        for (int ks = 0; ks < 4; ++ks) {
            uint32_t af[4][4], bf[2][4];
#pragma unroll
            for (int mt = 0; mt < 4; ++mt) {
                int r = wr * 64 + mt * 16 + a_r;
                int u = ks * 2 + a_kb;
                ldm_x4(af[mt], st + OFF_A + r * 128 + ((u ^ (r & 7)) << 4));
            }
#pragma unroll
            for (int np = 0; np < 2; ++np) {
                int n = wc * 32 + np * 16 + b_r;
                int u = ks * 2 + b_kb;
                ldm_x4(bf[np], st + OFF_B + n * 128 + ((u ^ (n & 7)) << 4));
            }
#pragma unroll
            for (int mt = 0; mt < 4; ++mt)
#pragma unroll
                for (int nt = 0; nt < 4; ++nt) {
                    uint32_t bb[2] = { bf[nt >> 1][(nt & 1) * 2],
                                       bf[nt >> 1][(nt & 1) * 2 + 1] };
                    mma_16816(acc[mt][nt], af[mt], bb);
                }
        }
        __syncthreads();
    }

    // fused epilogue: bias + gate transform + packed half2(a,b) store
    const int g = lid >> 2, tig = lid & 3;
#pragma unroll
    for (int mt = 0; mt < 4; ++mt) {
        int row0 = rowBase + wr * 64 + mt * 16 + g;
#pragma unroll
        for (int nt = 0; nt < 4; ++nt) {
            int p = ((colBase + wc * 32 + nt * 8) >> 1) + tig;
            float bg = bias[p], bh = bias[HID + p];
            float* c = acc[mt][nt];
            ab[(size_t)row0 * HID + p]       = gate2ab(c[0] + bg, c[1] + bh);
            ab[(size_t)(row0 + 8) * HID + p] = gate2ab(c[2] + bg, c[3] + bh);
        }
    }
}

// ---------------------------------------------------------------------------
// fp32 -> fp16 tiled+swizzled. PAIR=true interleaves W rows (gate_p, hid_p).
// ---------------------------------------------------------------------------
template <int TR, bool PAIR>
__global__ void conv_tiled(const float* __restrict__ in,
                           uint4* __restrict__ hi, int nunits) {
    int i = blockIdx.x * blockDim.x + threadIdx.x;
    if (i >= nunits) return;
    int m  = i >> 7;
    int ku = i & 127;
    int kc = ku >> 3, u = ku & 7;
    int dm = PAIR ? (2 * (m & (HID - 1)) + (m >> 10)) : m;
    int mb = dm / TR, r = dm % TR;

    const float4* p = (const float4*)(in + (size_t)m * K_ + ku * 8);
    float4 v0 = p[0], v1 = p[1];
    float vv[8] = {v0.x, v0.y, v0.z, v0.w, v1.x, v1.y, v1.z, v1.w};

    uint32_t hw[4];
#pragma unroll
    for (int j = 0; j < 4; ++j) {
        __half h0 = __float2half_rn(vv[2 * j]);
        __half h1 = __float2half_rn(vv[2 * j + 1]);
        hw[j] = (uint32_t)__half_as_ushort(h0) |
                ((uint32_t)__half_as_ushort(h1) << 16);
    }
    size_t tile = ((size_t)mb * NCHUNK + kc) * (TR * 8);
    hi[tile + r * 8 + (u ^ (r & 7))] = make_uint4(hw[0], hw[1], hw[2], hw[3]);
}

// ---------------------------------------------------------------------------
// Phase 1: per-chunk (A,B) summaries, 8 channels/thread. grid (8, NCK) x 128
// ---------------------------------------------------------------------------
__global__ void __launch_bounds__(128) scan_sum() {
    const int cg = blockIdx.x * 128 + threadIdx.x;   // 0..1023
    const int ck = blockIdx.y;
    const int b = cg >> 7;
    const int hid0 = (cg & 127) * 8;
    const size_t rowbase = (size_t)b * S_ + ck * CKS;

    float A[8], Bc[8];
#pragma unroll
    for (int j = 0; j < 8; ++j) { A[j] = 1.f; Bc[j] = 0.f; }

#pragma unroll 4
    for (int s = 0; s < CKS; ++s) {
        const uint4* abp = (const uint4*)(g_ab + (rowbase + s) * HID + hid0);
        uint4 u0 = abp[0], u1 = abp[1];
        uint32_t uw[8] = {u0.x, u0.y, u0.z, u0.w, u1.x, u1.y, u1.z, u1.w};
#pragma unroll
        for (int j = 0; j < 8; ++j) {
            __half2 h2 = *(__half2*)&uw[j];
            float a = __low2float(h2), bv = __high2float(h2);
            Bc[j] = fmaf(a, Bc[j], bv);
            A[j] *= a;
        }
    }
    const int ch0 = b * HID + hid0;
#pragma unroll
    for (int j = 0; j < 8; ++j) {
        g_sumA[(ch0 + j) * NCK + ck] = A[j];
        g_sumB[(ch0 + j) * NCK + ck] = Bc[j];
    }
}

// ---------------------------------------------------------------------------
// Phase 2: 64-chunk scan per channel; one warp per channel, 2 chunks/lane.
// ---------------------------------------------------------------------------
__global__ void __launch_bounds__(256) scan_phase2(const float* __restrict__ h0) {
    const int gt = blockIdx.x * 256 + threadIdx.x;
    const int ch = gt >> 5;
    const int lane = gt & 31;

    float2 a2 = ((const float2*)(g_sumA + ch * NCK))[lane];
    float2 b2 = ((const float2*)(g_sumB + ch * NCK))[lane];
    float A0 = a2.x, B0 = b2.x;      // chunk 2*lane
    float A1 = a2.y, B1 = b2.y;      // chunk 2*lane+1

    float A = A1 * A0;
    float Bv = fmaf(A1, B0, B1);
#pragma unroll
    for (int off = 1; off < 32; off <<= 1) {
        float pA = __shfl_up_sync(0xFFFFFFFF, A, off);
        float pB = __shfl_up_sync(0xFFFFFFFF, Bv, off);
        if (lane >= off) {
            Bv = fmaf(A, pB, Bv);
            A  = pA * A;
        }
    }
    float eA = __shfl_up_sync(0xFFFFFFFF, A, 1);
    float eB = __shfl_up_sync(0xFFFFFFFF, Bv, 1);
    if (lane == 0) { eA = 1.f; eB = 0.f; }

    float x = h0[ch];
    float h0g = (x >= 0.f) ? (x + 0.5f)
                           : __fdividef(__expf(x), 1.f + __expf(x));
    float s0 = fmaf(eA, h0g, eB);     // start of chunk 2*lane
    float s1 = fmaf(A0, s0, B0);      // start of chunk 2*lane+1
    g_start[(2 * lane) * CH_ + ch]     = s0;
    g_start[(2 * lane + 1) * CH_ + ch] = s1;
}

// ---------------------------------------------------------------------------
// Phase 3: 8 channels/thread local scan + residual; optionally emits next
// layer's tiled fp16 A. grid (8, NCK) x 128.
// ---------------------------------------------------------------------------
template <bool EMIT_A>
__global__ void __launch_bounds__(128)
scan_phase3(const float* __restrict__ resid, float* __restrict__ outp,
            float* __restrict__ finals) {
    const int cg = blockIdx.x * 128 + threadIdx.x;   // 0..1023
    const int ck = blockIdx.y;
    const int b = cg >> 7;
    const int ku = cg & 127;
    const int hid0 = ku * 8;
    const int ch0 = b * HID + hid0;
    const size_t rowbase = (size_t)b * S_ + ck * CKS;
    const int kc = ku >> 3, uu = ku & 7;

    float h[8];
    {
        const float4* sp = (const float4*)(g_start + ck * CH_ + ch0);
        float4 s0 = sp[0], s1 = sp[1];
        h[0] = s0.x; h[1] = s0.y; h[2] = s0.z; h[3] = s0.w;
        h[4] = s1.x; h[5] = s1.y; h[6] = s1.z; h[7] = s1.w;
    }

#pragma unroll 4
    for (int s = 0; s < CKS; ++s) {
        size_t row = rowbase + s;
        const uint4* abp = (const uint4*)(g_ab + row * HID + hid0);
        uint4 u0 = abp[0], u1 = abp[1];
        const float4* rp = (const float4*)(resid + row * HID + hid0);
        float4 r0 = rp[0], r1 = rp[1];

        uint32_t uw[8] = {u0.x, u0.y, u0.z, u0.w, u1.x, u1.y, u1.z, u1.w};
        float rr[8] = {r0.x, r0.y, r0.z, r0.w, r1.x, r1.y, r1.z, r1.w};
        float ov[8];
#pragma unroll
        for (int j = 0; j < 8; ++j) {
            __half2 h2 = *(__half2*)&uw[j];
            h[j] = fmaf(__low2float(h2), h[j], __high2float(h2));
            ov[j] = h[j] + rr[j];
        }
        float4* op = (float4*)(outp + row * HID + hid0);
        op[0] = make_float4(ov[0], ov[1], ov[2], ov[3]);
        op[1] = make_float4(ov[4], ov[5], ov[6], ov[7]);

        if (EMIT_A) {
            uint32_t hw[4];
#pragma unroll
            for (int j = 0; j < 4; ++j) {
                __half a0 = __float2half_rn(ov[2 * j]);
                __half a1 = __float2half_rn(ov[2 * j + 1]);
                hw[j] = (uint32_t)__half_as_ushort(a0) |
                        ((uint32_t)__half_as_ushort(a1) << 16);
            }
            int mb = (int)(row >> 7), r = (int)(row & 127);
            g_Ah[((size_t)mb * NCHUNK + kc) * 1024 + r * 8 + (uu ^ (r & 7))] =
                make_uint4(hw[0], hw[1], hw[2], hw[3]);
        }
    }

    if (ck == NCK - 1) {
        float4* fp = (float4*)(finals + ch0);
        fp[0] = make_float4(h[0], h[1], h[2], h[3]);
        fp[1] = make_float4(h[4], h[5], h[6], h[7]);
    }
}

// ---------------------------------------------------------------------------
// Launcher
// ---------------------------------------------------------------------------
extern "C" void kernel_launch(void* const* d_in, const int* in_sizes, int n_in,
                              void* d_out, int out_size) {
    const float* x  = (const float*)d_in[0];
    const float* h  = (const float*)d_in[1];
    const float* W0 = (const float*)d_in[2];
    const float* b0 = (const float*)d_in[3];
    const float* Wl = (const float*)d_in[4];
    const float* bl = (const float*)d_in[5];

    float* out    = (float*)d_out;
    float* finals = out + (size_t)M_ * HID;

    float* inp;
    uint32_t* ab;
    uint4 *Ah, *Wh;
    cudaGetSymbolAddress((void**)&inp, g_inp);
    cudaGetSymbolAddress((void**)&ab,  g_ab);
    cudaGetSymbolAddress((void**)&Ah,  g_Ah);
    cudaGetSymbolAddress((void**)&Wh,  g_Wh);

    cudaFuncSetAttribute(gemm_mma, cudaFuncAttributeMaxDynamicSharedMemorySize,
                         SMEM_BYTES);

    const int nAu = M_ * K_ / 8;
    const int nWu = N_ * K_ / 8;   // per-layer W units
    dim3 ggrid(N_ / BN, M_ / BM);     // (8, 128)
    dim3 sgrid(8, NCK);               // (8, 64)

    // all W conversions + layer-0 A conversion upfront
    conv_tiled<BM, false><<<(nAu + 255) / 256, 256>>>(x, Ah, nAu);
    conv_tiled<BN, true><<<(nWu + 255) / 256, 256>>>(W0, Wh, nWu);
    for (int l = 1; l < L_; ++l)
        conv_tiled<BN, true><<<(nWu + 255) / 256, 256>>>(
            Wl + (size_t)(l - 1) * N_ * K_, Wh + (size_t)l * nWu, nWu);

    for (int l = 0; l < L_; ++l) {
        const float* b = (l == 0) ? b0 : (bl + (size_t)(l - 1) * N_);
        const float* src = (l == 0) ? x : inp;

        gemm_mma<<<ggrid, GTHREADS, SMEM_BYTES>>>(
            (const char*)Ah, (const char*)(Wh + (size_t)l * nWu), b, ab);

        scan_sum<<<sgrid, 128>>>();
        scan_phase2<<<CH_ * 32 / 256, 256>>>(h + (size_t)l * CH_);
        float* ob = (l == L_ - 1) ? out : inp;
        if (l == L_ - 1)
            scan_phase3<false><<<sgrid, 128>>>(src, ob,
                                               finals + (size_t)l * CH_);
        else
            scan_phase3<true><<<sgrid, 128>>>(src, ob,
                                              finals + (size_t)l * CH_);
    }
}

// round 16
// speedup vs baseline: 2.7368x; 1.0672x over previous
#include <cuda_runtime.h>
#include <cuda_fp16.h>
#include <math.h>
#include <stdint.h>

// ---------------- problem constants ----------------
#define B_  8
#define S_  2048
#define HID 1024
#define L_  4
#define M_  (B_ * S_)    // 16384
#define N_  (2 * HID)    // 2048
#define K_  1024
#define CH_ 8192         // B*H channels
#define NCK 64           // scan chunks
#define CKS 32           // steps per chunk

// ---------------- GEMM tiling ----------------
#define BM 128
#define BN 128
#define NCHUNK 16        // K_/64
#define STAGES 3
#define GTHREADS 256

#define STAGE_BYTES 32768          // A 16K + B 16K
#define OFF_A 0
#define OFF_B 16384
#define SMEM_BYTES (1024 + STAGES * STAGE_BYTES)   // 99328 -> 2 CTAs/SM

#define A_TILE_B 16384   // 128x64 fp16
#define W_TILE_B 16384   // 128x64 fp16

// ---------------- scratch (allocation-free rule) ----------------
__device__ uint32_t g_ab[(size_t)M_ * HID];   // packed half2 (a, b)
__device__ float    g_inp[(size_t)M_ * HID];
__device__ float    g_sumA[CH_ * NCK];
__device__ float    g_sumB[CH_ * NCK];
__device__ float    g_start[CH_ * NCK];
__device__ uint4    g_Ah[(size_t)M_ * K_ / 8];
__device__ uint4    g_Wh[(size_t)L_ * N_ * K_ / 8];

// ---------------- helpers ----------------
__device__ __forceinline__ uint32_t smem_u32(const void* p) {
    uint32_t a;
    asm("{ .reg .u64 t; cvta.to.shared.u64 t, %1; cvt.u32.u64 %0, t; }"
        : "=r"(a) : "l"(p));
    return a;
}
__device__ __forceinline__ void bulk_g2s(uint32_t dst, const void* src,
                                         uint32_t bytes, uint32_t mbar) {
    asm volatile(
        "cp.async.bulk.shared::cta.global.mbarrier::complete_tx::bytes "
        "[%0], [%1], %2, [%3];"
        :: "r"(dst), "l"(src), "r"(bytes), "r"(mbar) : "memory");
}
#define MBAR_INIT(a, c) \
    asm volatile("mbarrier.init.shared.b64 [%0], %1;" :: "r"(a), "r"((uint32_t)(c)) : "memory")
#define MBAR_EXPECT(a, b) \
    asm volatile("mbarrier.arrive.expect_tx.shared.b64 _, [%0], %1;" \
                 :: "r"(a), "r"((uint32_t)(b)) : "memory")
#define MBAR_WAIT(a, ph) do {                                                    \
    asm volatile(                                                                 \
        "{ .reg .pred P;\n"                                                       \
        "LAB_%=: mbarrier.try_wait.parity.acquire.cta.shared::cta.b64 P, [%0], %1, 0x989680;\n" \
        "@P bra.uni DONE_%=;\n"                                                   \
        "bra.uni LAB_%=;\n"                                                       \
        "DONE_%=: }"                                                              \
        :: "r"(a), "r"((uint32_t)(ph)) : "memory");                               \
} while (0)

__device__ __forceinline__ void ldm_x4(uint32_t* r, uint32_t addr) {
    asm volatile("ldmatrix.sync.aligned.m8n8.x4.shared.b16 {%0,%1,%2,%3}, [%4];"
                 : "=r"(r[0]), "=r"(r[1]), "=r"(r[2]), "=r"(r[3]) : "r"(addr));
}
__device__ __forceinline__ void mma_16816(float* c, const uint32_t* a,
                                          const uint32_t* b) {
    asm volatile(
        "mma.sync.aligned.m16n8k16.row.col.f32.f16.f16.f32 "
        "{%0,%1,%2,%3}, {%4,%5,%6,%7}, {%8,%9}, {%0,%1,%2,%3};"
        : "+f"(c[0]), "+f"(c[1]), "+f"(c[2]), "+f"(c[3])
        : "r"(a[0]), "r"(a[1]), "r"(a[2]), "r"(a[3]), "r"(b[0]), "r"(b[1]));
}

// gate/hidden pair -> packed half2 (a, b)
__device__ __forceinline__ uint32_t gate2ab(float gate, float hd) {
    float e1 = __expf(fminf(gate, 60.f));
    float e2 = __expf(fminf(hd, 0.f));
    float d1 = 1.f + e1, d2 = 1.f + e2;
    float rr = __fdividef(1.f, d1 * d2);
    float a  = rr * d2;            // sigma(-gate)
    float s2 = e2 * rr * d1;       // sigma(hd)  [hd<0 path]
    float z  = 1.f - a;            // sigma(gate)
    float gg = (hd >= 0.f) ? (hd + 0.5f) : s2;
    float bv = z * gg;
    __half2 h2 = __floats2half2_rn(a, bv);
    return *(uint32_t*)&h2;
}

// ---------------------------------------------------------------------------
// fp16 GEMM with fused gate transform: ab[m][p] = f(A@W^T + bias)
// 256 threads, BM=128 x BN=128, warp tile 64x32, occ=2 (no spills at 128 regs)
// W rows pre-interleaved (gate_p, hidden_p).
// ---------------------------------------------------------------------------
__global__ void __launch_bounds__(GTHREADS, 2)
gemm_mma(const char* __restrict__ Ah, const char* __restrict__ Wh,
         const float* __restrict__ bias, uint32_t* __restrict__ ab) {
    extern __shared__ __align__(1024) char smem[];
    const uint32_t sb = smem_u32(smem);
    const int tid = threadIdx.x;
    const int wid = tid >> 5, lid = tid & 31;
    const int wr = wid & 1;          // 2 x 64 rows
    const int wc = wid >> 1;         // 4 x 32 cols
    const int rowBase = blockIdx.y * BM;
    const int colBase = blockIdx.x * BN;

    if (tid == 0) {
#pragma unroll
        for (int s = 0; s < STAGES; ++s) MBAR_INIT(sb + s * 8, 1);
    }
    __syncthreads();

    auto issue = [&](int kc, int s) {
        uint32_t bar = sb + s * 8;
        uint32_t st = sb + 1024 + s * STAGE_BYTES;
        MBAR_EXPECT(bar, STAGE_BYTES);
        bulk_g2s(st + OFF_A, Ah + ((size_t)blockIdx.y * NCHUNK + kc) * A_TILE_B,
                 A_TILE_B, bar);
        bulk_g2s(st + OFF_B, Wh + ((size_t)blockIdx.x * NCHUNK + kc) * W_TILE_B,
                 W_TILE_B, bar);
    };

    if (tid == 0) { issue(0, 0); issue(1, 1); }

    float acc[4][4][4];
#pragma unroll
    for (int i = 0; i < 4; ++i)
#pragma unroll
        for (int j = 0; j < 4; ++j)
#pragma unroll
            for (int k = 0; k < 4; ++k) acc[i][j][k] = 0.f;

    const int a_r  = (lid & 7) + ((lid >> 3) & 1) * 8;
    const int a_kb = lid >> 4;
    const int b_r  = (lid & 7) + ((lid >> 4) & 1) * 8;
    const int b_kb = (lid >> 3) & 1;

    int ph[STAGES] = {0, 0, 0};

    for (int kt = 0; kt < NCHUNK; ++kt) {
        const int s = kt % STAGES;
        MBAR_WAIT(sb + s * 8, ph[s]);
        ph[s] ^= 1;
        if (tid == 0 && kt + 2 < NCHUNK) issue(kt + 2, (kt + 2) % STAGES);

        const uint32_t st = sb + 1024 + s * STAGE_BYTES;
#pragma unroll
        for (int ks = 0; ks < 4; ++ks) {
            uint32_t af[4][4], bf[2][4];
#pragma unroll
            for (int mt = 0; mt < 4; ++mt) {
                int r = wr * 64 + mt * 16 + a_r;
                int u = ks * 2 + a_kb;
                ldm_x4(af[mt], st + OFF_A + r * 128 + ((u ^ (r & 7)) << 4));
            }
#pragma unroll
            for (int np = 0; np < 2; ++np) {
                int n = wc * 32 + np * 16 + b_r;
                int u = ks * 2 + b_kb;
                ldm_x4(bf[np], st + OFF_B + n * 128 + ((u ^ (n & 7)) << 4));
            }
#pragma unroll
            for (int mt = 0; mt < 4; ++mt)
#pragma unroll
                for (int nt = 0; nt < 4; ++nt) {
                    uint32_t bb[2] = { bf[nt >> 1][(nt & 1) * 2],
                                       bf[nt >> 1][(nt & 1) * 2 + 1] };
                    mma_16816(acc[mt][nt], af[mt], bb);
                }
        }
        __syncthreads();
    }

    // fused epilogue: bias + gate transform + packed half2(a,b) store
    const int g = lid >> 2, tig = lid & 3;
#pragma unroll
    for (int mt = 0; mt < 4; ++mt) {
        int row0 = rowBase + wr * 64 + mt * 16 + g;
#pragma unroll
        for (int nt = 0; nt < 4; ++nt) {
            int p = ((colBase + wc * 32 + nt * 8) >> 1) + tig;
            float bg = bias[p], bh = bias[HID + p];
            float* c = acc[mt][nt];
            ab[(size_t)row0 * HID + p]       = gate2ab(c[0] + bg, c[1] + bh);
            ab[(size_t)(row0 + 8) * HID + p] = gate2ab(c[2] + bg, c[3] + bh);
        }
    }
}

// ---------------------------------------------------------------------------
// fp32 -> fp16 tiled+swizzled. PAIR=true interleaves W rows (gate_p, hid_p).
// ---------------------------------------------------------------------------
template <int TR, bool PAIR>
__global__ void conv_tiled(const float* __restrict__ in,
                           uint4* __restrict__ hi, int nunits) {
    int i = blockIdx.x * blockDim.x + threadIdx.x;
    if (i >= nunits) return;
    int m  = i >> 7;
    int ku = i & 127;
    int kc = ku >> 3, u = ku & 7;
    int dm = PAIR ? (2 * (m & (HID - 1)) + (m >> 10)) : m;
    int mb = dm / TR, r = dm % TR;

    const float4* p = (const float4*)(in + (size_t)m * K_ + ku * 8);
    float4 v0 = p[0], v1 = p[1];
    float vv[8] = {v0.x, v0.y, v0.z, v0.w, v1.x, v1.y, v1.z, v1.w};

    uint32_t hw[4];
#pragma unroll
    for (int j = 0; j < 4; ++j) {
        __half h0 = __float2half_rn(vv[2 * j]);
        __half h1 = __float2half_rn(vv[2 * j + 1]);
        hw[j] = (uint32_t)__half_as_ushort(h0) |
                ((uint32_t)__half_as_ushort(h1) << 16);
    }
    size_t tile = ((size_t)mb * NCHUNK + kc) * (TR * 8);
    hi[tile + r * 8 + (u ^ (r & 7))] = make_uint4(hw[0], hw[1], hw[2], hw[3]);
}

// ---------------------------------------------------------------------------
// Phase 1: per-chunk (A,B) summaries, 8 channels/thread. grid (8, NCK) x 128
// ---------------------------------------------------------------------------
__global__ void __launch_bounds__(128) scan_sum() {
    const int cg = blockIdx.x * 128 + threadIdx.x;   // 0..1023
    const int ck = blockIdx.y;
    const int b = cg >> 7;
    const int hid0 = (cg & 127) * 8;
    const size_t rowbase = (size_t)b * S_ + ck * CKS;

    float A[8], Bc[8];
#pragma unroll
    for (int j = 0; j < 8; ++j) { A[j] = 1.f; Bc[j] = 0.f; }

#pragma unroll 4
    for (int s = 0; s < CKS; ++s) {
        const uint4* abp = (const uint4*)(g_ab + (rowbase + s) * HID + hid0);
        uint4 u0 = abp[0], u1 = abp[1];
        uint32_t uw[8] = {u0.x, u0.y, u0.z, u0.w, u1.x, u1.y, u1.z, u1.w};
#pragma unroll
        for (int j = 0; j < 8; ++j) {
            __half2 h2 = *(__half2*)&uw[j];
            float a = __low2float(h2), bv = __high2float(h2);
            Bc[j] = fmaf(a, Bc[j], bv);
            A[j] *= a;
        }
    }
    const int ch0 = b * HID + hid0;
#pragma unroll
    for (int j = 0; j < 8; ++j) {
        g_sumA[(ch0 + j) * NCK + ck] = A[j];
        g_sumB[(ch0 + j) * NCK + ck] = Bc[j];
    }
}

// ---------------------------------------------------------------------------
// Phase 2: 64-chunk scan per channel; one warp per channel, 2 chunks/lane.
// ---------------------------------------------------------------------------
__global__ void __launch_bounds__(256) scan_phase2(const float* __restrict__ h0) {
    const int gt = blockIdx.x * 256 + threadIdx.x;
    const int ch = gt >> 5;
    const int lane = gt & 31;

    float2 a2 = ((const float2*)(g_sumA + ch * NCK))[lane];
    float2 b2 = ((const float2*)(g_sumB + ch * NCK))[lane];
    float A0 = a2.x, B0 = b2.x;      // chunk 2*lane
    float A1 = a2.y, B1 = b2.y;      // chunk 2*lane+1

    float A = A1 * A0;
    float Bv = fmaf(A1, B0, B1);
#pragma unroll
    for (int off = 1; off < 32; off <<= 1) {
        float pA = __shfl_up_sync(0xFFFFFFFF, A, off);
        float pB = __shfl_up_sync(0xFFFFFFFF, Bv, off);
        if (lane >= off) {
            Bv = fmaf(A, pB, Bv);
            A  = pA * A;
        }
    }
    float eA = __shfl_up_sync(0xFFFFFFFF, A, 1);
    float eB = __shfl_up_sync(0xFFFFFFFF, Bv, 1);
    if (lane == 0) { eA = 1.f; eB = 0.f; }

    float x = h0[ch];
    float h0g = (x >= 0.f) ? (x + 0.5f)
                           : __fdividef(__expf(x), 1.f + __expf(x));
    float s0 = fmaf(eA, h0g, eB);     // start of chunk 2*lane
    float s1 = fmaf(A0, s0, B0);      // start of chunk 2*lane+1
    g_start[(2 * lane) * CH_ + ch]     = s0;
    g_start[(2 * lane + 1) * CH_ + ch] = s1;
}

// ---------------------------------------------------------------------------
// Phase 3: 8 channels/thread local scan + residual; optionally emits next
// layer's tiled fp16 A. grid (8, NCK) x 128.
// ---------------------------------------------------------------------------
template <bool EMIT_A>
__global__ void __launch_bounds__(128)
scan_phase3(const float* __restrict__ resid, float* __restrict__ outp,
            float* __restrict__ finals) {
    const int cg = blockIdx.x * 128 + threadIdx.x;   // 0..1023
    const int ck = blockIdx.y;
    const int b = cg >> 7;
    const int ku = cg & 127;
    const int hid0 = ku * 8;
    const int ch0 = b * HID + hid0;
    const size_t rowbase = (size_t)b * S_ + ck * CKS;
    const int kc = ku >> 3, uu = ku & 7;

    float h[8];
    {
        const float4* sp = (const float4*)(g_start + ck * CH_ + ch0);
        float4 s0 = sp[0], s1 = sp[1];
        h[0] = s0.x; h[1] = s0.y; h[2] = s0.z; h[3] = s0.w;
        h[4] = s1.x; h[5] = s1.y; h[6] = s1.z; h[7] = s1.w;
    }

#pragma unroll 4
    for (int s = 0; s < CKS; ++s) {
        size_t row = rowbase + s;
        const uint4* abp = (const uint4*)(g_ab + row * HID + hid0);
        uint4 u0 = abp[0], u1 = abp[1];
        const float4* rp = (const float4*)(resid + row * HID + hid0);
        float4 r0 = rp[0], r1 = rp[1];

        uint32_t uw[8] = {u0.x, u0.y, u0.z, u0.w, u1.x, u1.y, u1.z, u1.w};
        float rr[8] = {r0.x, r0.y, r0.z, r0.w, r1.x, r1.y, r1.z, r1.w};
        float ov[8];
#pragma unroll
        for (int j = 0; j < 8; ++j) {
            __half2 h2 = *(__half2*)&uw[j];
            h[j] = fmaf(__low2float(h2), h[j], __high2float(h2));
            ov[j] = h[j] + rr[j];
        }
        float4* op = (float4*)(outp + row * HID + hid0);
        op[0] = make_float4(ov[0], ov[1], ov[2], ov[3]);
        op[1] = make_float4(ov[4], ov[5], ov[6], ov[7]);

        if (EMIT_A) {
            uint32_t hw[4];
#pragma unroll
            for (int j = 0; j < 4; ++j) {
                __half a0 = __float2half_rn(ov[2 * j]);
                __half a1 = __float2half_rn(ov[2 * j + 1]);
                hw[j] = (uint32_t)__half_as_ushort(a0) |
                        ((uint32_t)__half_as_ushort(a1) << 16);
            }
            int mb = (int)(row >> 7), r = (int)(row & 127);
            g_Ah[((size_t)mb * NCHUNK + kc) * 1024 + r * 8 + (uu ^ (r & 7))] =
                make_uint4(hw[0], hw[1], hw[2], hw[3]);
        }
    }

    if (ck == NCK - 1) {
        float4* fp = (float4*)(finals + ch0);
        fp[0] = make_float4(h[0], h[1], h[2], h[3]);
        fp[1] = make_float4(h[4], h[5], h[6], h[7]);
    }
}

// ---------------------------------------------------------------------------
// Launcher
// ---------------------------------------------------------------------------
extern "C" void kernel_launch(void* const* d_in, const int* in_sizes, int n_in,
                              void* d_out, int out_size) {
    const float* x  = (const float*)d_in[0];
    const float* h  = (const float*)d_in[1];
    const float* W0 = (const float*)d_in[2];
    const float* b0 = (const float*)d_in[3];
    const float* Wl = (const float*)d_in[4];
    const float* bl = (const float*)d_in[5];

    float* out    = (float*)d_out;
    float* finals = out + (size_t)M_ * HID;

    float* inp;
    uint32_t* ab;
    uint4 *Ah, *Wh;
    cudaGetSymbolAddress((void**)&inp, g_inp);
    cudaGetSymbolAddress((void**)&ab,  g_ab);
    cudaGetSymbolAddress((void**)&Ah,  g_Ah);
    cudaGetSymbolAddress((void**)&Wh,  g_Wh);

    cudaFuncSetAttribute(gemm_mma, cudaFuncAttributeMaxDynamicSharedMemorySize,
                         SMEM_BYTES);

    const int nAu = M_ * K_ / 8;
    const int nWu = N_ * K_ / 8;   // per-layer W units
    dim3 ggrid(N_ / BN, M_ / BM);     // (16, 128)
    dim3 sgrid(8, NCK);               // (8, 64)

    // all W conversions + layer-0 A conversion upfront
    conv_tiled<BM, false><<<(nAu + 255) / 256, 256>>>(x, Ah, nAu);
    conv_tiled<BN, true><<<(nWu + 255) / 256, 256>>>(W0, Wh, nWu);
    for (int l = 1; l < L_; ++l)
        conv_tiled<BN, true><<<(nWu + 255) / 256, 256>>>(
            Wl + (size_t)(l - 1) * N_ * K_, Wh + (size_t)l * nWu, nWu);

    for (int l = 0; l < L_; ++l) {
        const float* b = (l == 0) ? b0 : (bl + (size_t)(l - 1) * N_);
        const float* src = (l == 0) ? x : inp;

        gemm_mma<<<ggrid, GTHREADS, SMEM_BYTES>>>(
            (const char*)Ah, (const char*)(Wh + (size_t)l * nWu), b, ab);

        scan_sum<<<sgrid, 128>>>();
        scan_phase2<<<CH_ * 32 / 256, 256>>>(h + (size_t)l * CH_);
        float* ob = (l == L_ - 1) ? out : inp;
        if (l == L_ - 1)
            scan_phase3<false><<<sgrid, 128>>>(src, ob,
                                               finals + (size_t)l * CH_);
        else
            scan_phase3<true><<<sgrid, 128>>>(src, ob,
                                              finals + (size_t)l * CH_);
    }
}